// round 7
// baseline (speedup 1.0000x reference)
#include <cuda_runtime.h>

// Problem constants: B=64, H=64, W=64, n=256, NF=513, L=63*63=3969, alpha^2=25

__device__ float g_state[64 * 64 * 64 * 256];   // [cell=(i*64+j)][b][n]
__device__ float g_A[64 * 513 * 520];           // augmented [513 x 514] per batch, ld=520

// ---- packed f32x2 helpers (dual fp32 pipe) ---------------------------------
__device__ __forceinline__ unsigned long long pk2(float a, float b) {
    unsigned long long r;
    asm("mov.b64 %0,{%1,%2};" : "=l"(r) : "f"(a), "f"(b));
    return r;
}
__device__ __forceinline__ void fma2(unsigned long long& d,
                                     unsigned long long a, unsigned long long b) {
    asm("fma.rn.f32x2 %0,%1,%2,%0;" : "+l"(d) : "l"(a), "l"(b));
}
__device__ __forceinline__ void unpk2(unsigned long long v, float& a, float& b) {
    asm("mov.b64 {%0,%1},%2;" : "=f"(a), "=f"(b) : "l"(v));
}

// ---------------------------------------------------------------------------
// Phase 1: wavefront scan, one launch per anti-diagonal.
// Template BT = batch tile (16 or 32). 256 threads. Full n=256 per block.
// Thread tile: (BT/8) batches x 8 features  ->  fma2-pipe-bound inner body.
// Per-output k order: ascending 0..511 (left then up) — bitwise == R2/R6.
// ---------------------------------------------------------------------------
template<int BT>
__global__ __launch_bounds__(256) void scan_diag(
    const float* __restrict__ x, const float* __restrict__ Win,
    const float* __restrict__ W1, const float* __restrict__ W2,
    int d, int i_min)
{
    constexpr int BPT = BT / 8;        // batches per thread (4 or 2)
    constexpr int IN_W = BT + 4;       // padded in_s row
    extern __shared__ float sm[];
    float* w_base  = sm;                    // [2][32][256]
    float* in_base = sm + 2 * 32 * 256;     // [2][32][IN_W]

    const int i = i_min + (int)blockIdx.x;
    const int j = d - i;
    const int b0 = (int)blockIdx.y * BT;
    const int tid = (int)threadIdx.x;
    const int tx = tid & 31;           // n-group: 8 floats at tx*8
    const int ty = tid >> 5;           // batch group: BPT batches at ty*BPT

    const bool hasL = (j > 0);
    const bool hasU = (i > 0);
    const int cellL = hasL ? ((i * 64 + (j - 1)) * 64) : 0;
    const int cellU = hasU ? (((i - 1) * 64 + j) * 64) : 0;

    const int bb = tid >> 3;           // staging batch (valid when tid < BT*8)
    const int kq = tid & 7;            // staging k-quad

    unsigned long long acc[BPT][4];
#pragma unroll
    for (int p = 0; p < BPT; ++p)
#pragma unroll
        for (int c = 0; c < 4; ++c) acc[p][c] = 0ull;

    float4 inr;
    float4 wr[8];

    auto LOADC = [&](int kc) {
        const int k0 = kc * 32;
        const bool isLeft = (k0 < 256);
        const bool has = isLeft ? hasL : hasU;
        const int ks = isLeft ? k0 : (k0 - 256);
        if (tid < BT * 8) {
            inr = make_float4(0.f, 0.f, 0.f, 0.f);
            if (has) {
                const int cell = isLeft ? cellL : cellU;
                inr = *(const float4*)&g_state[(cell + b0 + bb) * 256 + ks + kq * 4];
            }
        }
        const float* __restrict__ Wm = isLeft ? W1 : W2;
#pragma unroll
        for (int t = 0; t < 8; ++t) {
            int fi = tid + t * 256;
            int kl = fi >> 6;
            int cq = fi & 63;
            wr[t] = *(const float4*)&Wm[(ks + kl) * 256 + cq * 4];
        }
    };
    auto STOREC = [&](int buf) {
        if (tid < BT * 8) {
            float* ip = in_base + (buf * 32 + kq * 4) * IN_W + bb;
            ip[0 * IN_W] = inr.x;
            ip[1 * IN_W] = inr.y;
            ip[2 * IN_W] = inr.z;
            ip[3 * IN_W] = inr.w;
        }
#pragma unroll
        for (int t = 0; t < 8; ++t) {
            int fi = tid + t * 256;
            int kl = fi >> 6;
            int cq = fi & 63;
            *(float4*)&w_base[(buf * 32 + kl) * 256 + cq * 4] = wr[t];
        }
    };

    LOADC(0);
    STOREC(0);

    for (int kc = 0; kc < 16; ++kc) {
        __syncthreads();
        if (kc < 15) LOADC(kc + 1);
        const float* wrow = w_base + ((kc & 1) * 32) * 256;
        const float* irow = in_base + ((kc & 1) * 32) * IN_W;
#pragma unroll 4
        for (int kl = 0; kl < 32; ++kl) {
            float av[BPT];
#pragma unroll
            for (int p = 0; p < BPT / 2; ++p) {
                float2 t2 = *(const float2*)&irow[kl * IN_W + ty * BPT + 2 * p];
                av[2 * p] = t2.x;
                av[2 * p + 1] = t2.y;
            }
            ulonglong2 wA = *(const ulonglong2*)&wrow[kl * 256 + tx * 8];
            ulonglong2 wB = *(const ulonglong2*)&wrow[kl * 256 + tx * 8 + 4];
#pragma unroll
            for (int p = 0; p < BPT; ++p) {
                unsigned long long s = pk2(av[p], av[p]);
                fma2(acc[p][0], s, wA.x);
                fma2(acc[p][1], s, wA.y);
                fma2(acc[p][2], s, wB.x);
                fma2(acc[p][3], s, wB.y);
            }
        }
        if (kc < 15) STOREC((kc + 1) & 1);
    }

    // epilogue: + x*Win, tanh, store
    const int cell = (i * 64 + j) * 64;
    const float4 win0 = *(const float4*)&Win[tx * 8];
    const float4 win1 = *(const float4*)&Win[tx * 8 + 4];
#pragma unroll
    for (int p = 0; p < BPT; ++p) {
        const int b = b0 + ty * BPT + p;
        const float xv = x[(b * 64 + i) * 64 + j];
        float v0, v1, v2, v3, v4, v5, v6, v7;
        unpk2(acc[p][0], v0, v1);
        unpk2(acc[p][1], v2, v3);
        unpk2(acc[p][2], v4, v5);
        unpk2(acc[p][3], v6, v7);
        float4 o0, o1;
        o0.x = tanhf(v0 + xv * win0.x); o0.y = tanhf(v1 + xv * win0.y);
        o0.z = tanhf(v2 + xv * win0.z); o0.w = tanhf(v3 + xv * win0.w);
        o1.x = tanhf(v4 + xv * win1.x); o1.y = tanhf(v5 + xv * win1.y);
        o1.z = tanhf(v6 + xv * win1.z); o1.w = tanhf(v7 + xv * win1.w);
        *(float4*)&g_state[(cell + b) * 256 + tx * 8] = o0;
        *(float4*)&g_state[(cell + b) * 256 + tx * 8 + 4] = o1;
    }
}

#define SCAN_SMEM_B32 ((2 * 32 * 256 + 2 * 32 * 36) * 4)
#define SCAN_SMEM_B16 ((2 * 32 * 256 + 2 * 32 * 20) * 4)

// ---------------------------------------------------------------------------
// Phase 2a: HtH tiles -> both triangles of A, += 25 on diagonal.
// Incremental (r,c) staging; values bitwise == R3/R5/R6 (passed).
// ---------------------------------------------------------------------------
__global__ __launch_bounds__(256) void hth_kernel()
{
    __shared__ __align__(16) float Hd[32][64];
    __shared__ __align__(16) float He[32][64];

    int rem = (int)blockIdx.x;
    int ti = 0;
    while (rem >= 9 - ti) { rem -= 9 - ti; ++ti; }
    const int tj = ti + rem;
    const int b = (int)blockIdx.y;
    const int d0 = ti * 64, e0 = tj * 64;
    const bool dLeft = d0 < 256, dOnes = d0 >= 512;
    const bool eLeft = e0 < 256, eOnes = e0 >= 512;
    const int dColn = dLeft ? d0 : d0 - 256;
    const int eColn = eLeft ? e0 : e0 - 256;

    const int tid = (int)threadIdx.x;
    const int tx = tid & 15, ty = tid >> 4;
    const int dd = tid & 63, kb = tid >> 6;

    int rs[8], cs[8];
#pragma unroll
    for (int t = 0; t < 8; ++t) { rs[t] = 0; cs[t] = kb + t * 4; }

    unsigned long long acc[2][4];
#pragma unroll
    for (int p = 0; p < 2; ++p)
#pragma unroll
        for (int c = 0; c < 4; ++c) acc[p][c] = 0ull;

    for (int l0 = 0; l0 < 3969; l0 += 32) {
        __syncthreads();
#pragma unroll
        for (int t = 0; t < 8; ++t) {
            const int kk = kb + t * 4;
            const int r = rs[t], c = cs[t];
            const bool valid = (r < 63);
            float vd, ve;
            if (dOnes) {
                vd = (valid && dd == 0) ? 1.f : 0.f;
            } else {
                int cellb = dLeft ? ((r + 1) * 64 + c) : (r * 64 + c + 1);
                vd = valid ? g_state[(cellb * 64 + b) * 256 + dColn + dd] : 0.f;
            }
            if (eOnes) {
                ve = (valid && dd == 0) ? 1.f : 0.f;
            } else {
                int cellb = eLeft ? ((r + 1) * 64 + c) : (r * 64 + c + 1);
                ve = valid ? g_state[(cellb * 64 + b) * 256 + eColn + dd] : 0.f;
            }
            Hd[kk][dd] = vd;
            He[kk][dd] = ve;
            int cn = c + 32, rn = r;
            if (cn >= 63) { cn -= 63; ++rn; }
            rs[t] = rn; cs[t] = cn;
        }
        __syncthreads();
#pragma unroll 8
        for (int kk = 0; kk < 32; ++kk) {
            unsigned long long a01 = *(const unsigned long long*)&Hd[kk][ty * 4];
            unsigned long long a23 = *(const unsigned long long*)&Hd[kk][ty * 4 + 2];
            float4 w = *(const float4*)&He[kk][tx * 4];
            unsigned long long wx = pk2(w.x, w.x);
            unsigned long long wy = pk2(w.y, w.y);
            unsigned long long wz = pk2(w.z, w.z);
            unsigned long long ww = pk2(w.w, w.w);
            fma2(acc[0][0], a01, wx); fma2(acc[0][1], a01, wy);
            fma2(acc[0][2], a01, wz); fma2(acc[0][3], a01, ww);
            fma2(acc[1][0], a23, wx); fma2(acc[1][1], a23, wy);
            fma2(acc[1][2], a23, wz); fma2(acc[1][3], a23, ww);
        }
    }

    float v[4][4];
#pragma unroll
    for (int p = 0; p < 2; ++p)
#pragma unroll
        for (int c = 0; c < 4; ++c)
            unpk2(acc[p][c], v[2 * p][c], v[2 * p + 1][c]);

    float* __restrict__ A = g_A + b * 513 * 520;
#pragma unroll
    for (int r = 0; r < 4; ++r) {
        int dr = d0 + ty * 4 + r;
        if (dr >= 513) continue;
#pragma unroll
        for (int c = 0; c < 4; ++c) {
            int e = e0 + tx * 4 + c;
            if (e >= 513) continue;
            float val = v[r][c];
            if (dr == e) val += 25.0f;
            A[dr * 520 + e] = val;
            if (ti != tj) A[e * 520 + dr] = val;
        }
    }
}

// ---------------------------------------------------------------------------
// Phase 2b: HtU -> column 513 of A.  EXACT R3 numerics (sequential (r,c) sum
// per column) — do NOT reassociate; the solve amplifies RHS perturbations.
// ---------------------------------------------------------------------------
__global__ __launch_bounds__(256) void htu_kernel(const float* __restrict__ x)
{
    const int b = (int)blockIdx.x;
    const int dcol = (int)blockIdx.y * 256 + (int)threadIdx.x;
    if (dcol >= 513) return;
    const float* __restrict__ xb = x + b * 4096;
    float acc = 0.f;
    if (dcol < 256) {
        for (int r = 0; r < 63; ++r)
            for (int c = 0; c < 63; ++c)
                acc += xb[(r + 1) * 64 + c + 1] *
                       g_state[(((r + 1) * 64 + c) * 64 + b) * 256 + dcol];
    } else if (dcol < 512) {
        const int d2 = dcol - 256;
        for (int r = 0; r < 63; ++r)
            for (int c = 0; c < 63; ++c)
                acc += xb[(r + 1) * 64 + c + 1] *
                       g_state[((r * 64 + (c + 1)) * 64 + b) * 256 + d2];
    } else {
        for (int r = 0; r < 63; ++r)
            for (int c = 0; c < 63; ++c)
                acc += xb[(r + 1) * 64 + c + 1];
    }
    g_A[(b * 513 + dcol) * 520 + 513] = acc;
}

// ---------------------------------------------------------------------------
// Phase 3: per-batch blocked LU (no pivoting; SPD) + back substitution.
// ---------------------------------------------------------------------------
__global__ __launch_bounds__(512) void solve_kernel(float* __restrict__ out)
{
    __shared__ float P[513 * 17];
    __shared__ __align__(16) float Us[16 * 132];
    __shared__ float red[16];

    const int b = (int)blockIdx.x;
    const int tid = (int)threadIdx.x;
    float* __restrict__ A = g_A + b * 513 * 520;

    for (int k0 = 0; k0 < 513; k0 += 16) {
        const int nb = (513 - k0) < 16 ? (513 - k0) : 16;
        const int nrows = 513 - k0;

        for (int idx = tid; idx < nrows * nb; idx += 512) {
            int rr = idx / nb, cc = idx - rr * nb;
            P[rr * 17 + cc] = A[(k0 + rr) * 520 + (k0 + cc)];
        }
        __syncthreads();

        for (int kk = 0; kk < nb; ++kk) {
            float inv = 1.0f / P[kk * 17 + kk];
            for (int rr = kk + 1 + tid; rr < nrows; rr += 512) {
                float lv = P[rr * 17 + kk] * inv;
                P[rr * 17 + kk] = lv;
                for (int cc = kk + 1; cc < nb; ++cc)
                    P[rr * 17 + cc] -= lv * P[kk * 17 + cc];
            }
            __syncthreads();
        }

        for (int idx = tid; idx < nrows * nb; idx += 512) {
            int rr = idx / nb, cc = idx - rr * nb;
            A[(k0 + rr) * 520 + (k0 + cc)] = P[rr * 17 + cc];
        }
        __syncthreads();

        const int cstart = k0 + nb;
        const int width = 514 - cstart;
        for (int ch = 0; ch < width; ch += 128) {
            int wlen = width - ch; if (wlen > 128) wlen = 128;
            const int wlenp = (wlen + 3) & ~3;
            const int cbase = cstart + ch;

            for (int idx = tid; idx < nb * wlenp; idx += 512) {
                int rr = idx / wlenp, cc = idx - rr * wlenp;
                Us[rr * 132 + cc] = A[(k0 + rr) * 520 + cbase + cc];
            }
            __syncthreads();

            for (int cc = tid; cc < wlenp; cc += 512) {
                float col[16];
                for (int m = 0; m < nb; ++m) col[m] = Us[m * 132 + cc];
                for (int kk = 1; kk < nb; ++kk) {
                    float v = col[kk];
                    for (int m = 0; m < kk; ++m) v -= P[kk * 17 + m] * col[m];
                    col[kk] = v;
                }
                for (int m = 0; m < nb; ++m) {
                    Us[m * 132 + cc] = col[m];
                    A[(k0 + m) * 520 + cbase + cc] = col[m];
                }
            }
            __syncthreads();

            const int trows = nrows - nb;
            const int npr = (trows + 1) >> 1;
            const int ncq = wlenp >> 2;
            for (int idx = tid; idx < npr * ncq; idx += 512) {
                int pr = idx / ncq, cq = idx - pr * ncq;
                int row0 = cstart + pr * 2;
                int cc = cq * 4;
                bool has2 = (pr * 2 + 1) < trows;
                const unsigned long long* pa0 =
                    (const unsigned long long*)&A[row0 * 520 + cbase + cc];
                const unsigned long long* pa1 =
                    (const unsigned long long*)&A[(row0 + 1) * 520 + cbase + cc];
                unsigned long long a00 = pa0[0], a01v = pa0[1];
                unsigned long long a10 = has2 ? pa1[0] : a00;
                unsigned long long a11 = has2 ? pa1[1] : a01v;
                const float* P0 = &P[(row0 - k0) * 17];
                const float* P1 = has2 ? (P0 + 17) : P0;
#pragma unroll
                for (int m = 0; m < 16; ++m) {
                    if (m < nb) {
                        const unsigned long long* pu =
                            (const unsigned long long*)&Us[m * 132 + cc];
                        unsigned long long u01 = pu[0], u23 = pu[1];
                        float p0 = P0[m], p1 = P1[m];
                        unsigned long long np0 = pk2(-p0, -p0);
                        unsigned long long np1 = pk2(-p1, -p1);
                        fma2(a00, u01, np0); fma2(a01v, u23, np0);
                        fma2(a10, u01, np1); fma2(a11, u23, np1);
                    }
                }
                unsigned long long* sa0 =
                    (unsigned long long*)&A[row0 * 520 + cbase + cc];
                sa0[0] = a00; sa0[1] = a01v;
                if (has2) {
                    unsigned long long* sa1 =
                        (unsigned long long*)&A[(row0 + 1) * 520 + cbase + cc];
                    sa1[0] = a10; sa1[1] = a11;
                }
            }
            __syncthreads();
        }
    }

    float* xs = P;
    const int lane = tid & 31, wid = tid >> 5;
    for (int r = 512; r >= 0; --r) {
        float part = 0.f;
        for (int c = r + 1 + tid; c <= 512; c += 512)
            part += A[r * 520 + c] * xs[c];
#pragma unroll
        for (int off = 16; off > 0; off >>= 1)
            part += __shfl_down_sync(0xffffffffu, part, off);
        if (lane == 0) red[wid] = part;
        __syncthreads();
        if (tid == 0) {
            float s = 0.f;
#pragma unroll
            for (int w2 = 0; w2 < 16; ++w2) s += red[w2];
            xs[r] = (A[r * 520 + 513] - s) / A[r * 520 + r];
        }
        __syncthreads();
    }
    for (int i2 = tid; i2 < 513; i2 += 512)
        out[b * 513 + i2] = xs[i2];
}

// ---------------------------------------------------------------------------
extern "C" void kernel_launch(void* const* d_in, const int* in_sizes, int n_in,
                              void* d_out, int out_size)
{
    const float* x   = (const float*)d_in[0];
    const float* Win = (const float*)d_in[1];
    const float* W1  = (const float*)d_in[2];
    const float* W2  = (const float*)d_in[3];
    float* out = (float*)d_out;

    cudaFuncSetAttribute(scan_diag<32>,
                         cudaFuncAttributeMaxDynamicSharedMemorySize, SCAN_SMEM_B32);
    cudaFuncSetAttribute(scan_diag<16>,
                         cudaFuncAttributeMaxDynamicSharedMemorySize, SCAN_SMEM_B16);

    for (int d = 0; d < 127; ++d) {
        int i_min = d > 63 ? d - 63 : 0;
        int cells = (d <= 63) ? (d + 1) : (127 - d);
        if (cells <= 36) {
            scan_diag<16><<<dim3(cells, 4), 256, SCAN_SMEM_B16>>>(x, Win, W1, W2, d, i_min);
        } else {
            scan_diag<32><<<dim3(cells, 2), 256, SCAN_SMEM_B32>>>(x, Win, W1, W2, d, i_min);
        }
    }
    hth_kernel<<<dim3(45, 64), 256>>>();
    htu_kernel<<<dim3(64, 3), 256>>>(x);
    solve_kernel<<<64, 512>>>(out);
}

// round 8
// speedup vs baseline: 1.1570x; 1.1570x over previous
#include <cuda_runtime.h>

// Problem constants: B=64, H=64, W=64, n=256, NF=513, L=63*63=3969, alpha^2=25

__device__ float g_state[64 * 64 * 64 * 256];   // [cell=(i*64+j)][b][n]
__device__ float g_A[64 * 513 * 520];           // augmented [513 x 514] per batch, ld=520

// ---- packed f32x2 helpers (dual fp32 pipe) ---------------------------------
__device__ __forceinline__ unsigned long long pk2(float a, float b) {
    unsigned long long r;
    asm("mov.b64 %0,{%1,%2};" : "=l"(r) : "f"(a), "f"(b));
    return r;
}
__device__ __forceinline__ void fma2(unsigned long long& d,
                                     unsigned long long a, unsigned long long b) {
    asm("fma.rn.f32x2 %0,%1,%2,%0;" : "+l"(d) : "l"(a), "l"(b));
}
__device__ __forceinline__ void unpk2(unsigned long long v, float& a, float& b) {
    asm("mov.b64 {%0,%1},%2;" : "=f"(a), "=f"(b) : "l"(v));
}

// ---------------------------------------------------------------------------
// Phase 1: wavefront scan, one launch per anti-diagonal.
// Block: 256 threads, 32 batches x 128 features, k-chunk 64 (8 chunks, 2-buf).
// Thread tile 2b x 8n -> body 13 instr / 8 fma2 (pipe-bound with slack).
// grid = (cells, 2 batch-halves, 2 n-halves).  smem 84 KB -> 2 blocks/SM.
// Per-output k order: ascending 0..511 (left then up) — bitwise == R2/R6.
// ---------------------------------------------------------------------------
#define SCAN_SMEM ((2 * 64 * 128 + 2 * 64 * 36) * 4)

__global__ __launch_bounds__(256) void scan_diag(
    const float* __restrict__ x, const float* __restrict__ Win,
    const float* __restrict__ W1, const float* __restrict__ W2,
    int d, int i_min)
{
    extern __shared__ float sm[];
    float* w_base  = sm;                    // [2][64][128]
    float* in_base = sm + 2 * 64 * 128;     // [2][64][36]  (k-major, batch minor)

    const int i = i_min + (int)blockIdx.x;
    const int j = d - i;
    const int b0 = (int)blockIdx.y * 32;
    const int n0 = (int)blockIdx.z * 128;
    const int tid = (int)threadIdx.x;
    const int tx = tid & 15;           // n-local: {tx*4..+3} and {64+tx*4..+3}
    const int ty = tid >> 4;           // batches b0 + ty*2, +1

    const bool hasL = (j > 0);
    const bool hasU = (i > 0);
    const int cellL = hasL ? ((i * 64 + (j - 1)) * 64) : 0;
    const int cellU = hasU ? (((i - 1) * 64 + j) * 64) : 0;

    const int bb = tid >> 3;           // 0..31 staging batch
    const int kq = tid & 7;            // 0..7  staging k-quad (x2 halves)

    unsigned long long acc[2][4];
#pragma unroll
    for (int p = 0; p < 2; ++p)
#pragma unroll
        for (int c = 0; c < 4; ++c) acc[p][c] = 0ull;

    float4 inr[2];
    float4 wr[8];

    auto LOADC = [&](int kc) {
        const int k0 = kc * 64;
        const bool isLeft = (k0 < 256);
        const bool has = isLeft ? hasL : hasU;
        const int ks = isLeft ? k0 : (k0 - 256);
        const int cell = isLeft ? cellL : cellU;
#pragma unroll
        for (int h = 0; h < 2; ++h) {
            inr[h] = make_float4(0.f, 0.f, 0.f, 0.f);
            if (has)
                inr[h] = *(const float4*)
                    &g_state[(cell + b0 + bb) * 256 + ks + (kq + 8 * h) * 4];
        }
        const float* __restrict__ Wm = isLeft ? W1 : W2;
#pragma unroll
        for (int t = 0; t < 8; ++t) {
            int fi = tid + t * 256;
            int kl = fi >> 5;          // 0..63
            int cq = fi & 31;          // 0..31
            wr[t] = *(const float4*)&Wm[(ks + kl) * 256 + n0 + cq * 4];
        }
    };
    auto STOREC = [&](int buf) {
#pragma unroll
        for (int h = 0; h < 2; ++h) {
            float* ip = in_base + (buf * 64 + (kq + 8 * h) * 4) * 36 + bb;
            ip[0 * 36] = inr[h].x;
            ip[1 * 36] = inr[h].y;
            ip[2 * 36] = inr[h].z;
            ip[3 * 36] = inr[h].w;
        }
#pragma unroll
        for (int t = 0; t < 8; ++t) {
            int fi = tid + t * 256;
            int kl = fi >> 5;
            int cq = fi & 31;
            *(float4*)&w_base[(buf * 64 + kl) * 128 + cq * 4] = wr[t];
        }
    };

    LOADC(0);
    STOREC(0);

    for (int kc = 0; kc < 8; ++kc) {
        __syncthreads();
        if (kc < 7) LOADC(kc + 1);
        const float* wrow = w_base + ((kc & 1) * 64) * 128;
        const float* irow = in_base + ((kc & 1) * 64) * 36;
#pragma unroll 8
        for (int kl = 0; kl < 64; ++kl) {
            float2 a = *(const float2*)&irow[kl * 36 + ty * 2];   // broadcast
            ulonglong2 wA = *(const ulonglong2*)&wrow[kl * 128 + tx * 4];
            ulonglong2 wB = *(const ulonglong2*)&wrow[kl * 128 + 64 + tx * 4];
            unsigned long long s0 = pk2(a.x, a.x);
            unsigned long long s1 = pk2(a.y, a.y);
            fma2(acc[0][0], s0, wA.x); fma2(acc[0][1], s0, wA.y);
            fma2(acc[0][2], s0, wB.x); fma2(acc[0][3], s0, wB.y);
            fma2(acc[1][0], s1, wA.x); fma2(acc[1][1], s1, wA.y);
            fma2(acc[1][2], s1, wB.x); fma2(acc[1][3], s1, wB.y);
        }
        if (kc < 7) STOREC((kc + 1) & 1);
    }

    // epilogue: + x*Win, tanh, store
    const int cell = (i * 64 + j) * 64;
    const float4 win0 = *(const float4*)&Win[n0 + tx * 4];
    const float4 win1 = *(const float4*)&Win[n0 + 64 + tx * 4];
#pragma unroll
    for (int p = 0; p < 2; ++p) {
        const int b = b0 + ty * 2 + p;
        const float xv = x[(b * 64 + i) * 64 + j];
        float v0, v1, v2, v3, v4, v5, v6, v7;
        unpk2(acc[p][0], v0, v1);
        unpk2(acc[p][1], v2, v3);
        unpk2(acc[p][2], v4, v5);
        unpk2(acc[p][3], v6, v7);
        float4 o0, o1;
        o0.x = tanhf(v0 + xv * win0.x); o0.y = tanhf(v1 + xv * win0.y);
        o0.z = tanhf(v2 + xv * win0.z); o0.w = tanhf(v3 + xv * win0.w);
        o1.x = tanhf(v4 + xv * win1.x); o1.y = tanhf(v5 + xv * win1.y);
        o1.z = tanhf(v6 + xv * win1.z); o1.w = tanhf(v7 + xv * win1.w);
        *(float4*)&g_state[(cell + b) * 256 + n0 + tx * 4] = o0;
        *(float4*)&g_state[(cell + b) * 256 + n0 + 64 + tx * 4] = o1;
    }
}

// ---------------------------------------------------------------------------
// Phase 2a: HtH tiles -> both triangles of A, += 25 on diagonal.
// Incremental (r,c) staging; values bitwise == R3/R5/R6/R7 (passed).
// ---------------------------------------------------------------------------
__global__ __launch_bounds__(256) void hth_kernel()
{
    __shared__ __align__(16) float Hd[32][64];
    __shared__ __align__(16) float He[32][64];

    int rem = (int)blockIdx.x;
    int ti = 0;
    while (rem >= 9 - ti) { rem -= 9 - ti; ++ti; }
    const int tj = ti + rem;
    const int b = (int)blockIdx.y;
    const int d0 = ti * 64, e0 = tj * 64;
    const bool dLeft = d0 < 256, dOnes = d0 >= 512;
    const bool eLeft = e0 < 256, eOnes = e0 >= 512;
    const int dColn = dLeft ? d0 : d0 - 256;
    const int eColn = eLeft ? e0 : e0 - 256;

    const int tid = (int)threadIdx.x;
    const int tx = tid & 15, ty = tid >> 4;
    const int dd = tid & 63, kb = tid >> 6;

    int rs[8], cs[8];
#pragma unroll
    for (int t = 0; t < 8; ++t) { rs[t] = 0; cs[t] = kb + t * 4; }

    unsigned long long acc[2][4];
#pragma unroll
    for (int p = 0; p < 2; ++p)
#pragma unroll
        for (int c = 0; c < 4; ++c) acc[p][c] = 0ull;

    for (int l0 = 0; l0 < 3969; l0 += 32) {
        __syncthreads();
#pragma unroll
        for (int t = 0; t < 8; ++t) {
            const int kk = kb + t * 4;
            const int r = rs[t], c = cs[t];
            const bool valid = (r < 63);
            float vd, ve;
            if (dOnes) {
                vd = (valid && dd == 0) ? 1.f : 0.f;
            } else {
                int cellb = dLeft ? ((r + 1) * 64 + c) : (r * 64 + c + 1);
                vd = valid ? g_state[(cellb * 64 + b) * 256 + dColn + dd] : 0.f;
            }
            if (eOnes) {
                ve = (valid && dd == 0) ? 1.f : 0.f;
            } else {
                int cellb = eLeft ? ((r + 1) * 64 + c) : (r * 64 + c + 1);
                ve = valid ? g_state[(cellb * 64 + b) * 256 + eColn + dd] : 0.f;
            }
            Hd[kk][dd] = vd;
            He[kk][dd] = ve;
            int cn = c + 32, rn = r;
            if (cn >= 63) { cn -= 63; ++rn; }
            rs[t] = rn; cs[t] = cn;
        }
        __syncthreads();
#pragma unroll 8
        for (int kk = 0; kk < 32; ++kk) {
            unsigned long long a01 = *(const unsigned long long*)&Hd[kk][ty * 4];
            unsigned long long a23 = *(const unsigned long long*)&Hd[kk][ty * 4 + 2];
            float4 w = *(const float4*)&He[kk][tx * 4];
            unsigned long long wx = pk2(w.x, w.x);
            unsigned long long wy = pk2(w.y, w.y);
            unsigned long long wz = pk2(w.z, w.z);
            unsigned long long ww = pk2(w.w, w.w);
            fma2(acc[0][0], a01, wx); fma2(acc[0][1], a01, wy);
            fma2(acc[0][2], a01, wz); fma2(acc[0][3], a01, ww);
            fma2(acc[1][0], a23, wx); fma2(acc[1][1], a23, wy);
            fma2(acc[1][2], a23, wz); fma2(acc[1][3], a23, ww);
        }
    }

    float v[4][4];
#pragma unroll
    for (int p = 0; p < 2; ++p)
#pragma unroll
        for (int c = 0; c < 4; ++c)
            unpk2(acc[p][c], v[2 * p][c], v[2 * p + 1][c]);

    float* __restrict__ A = g_A + b * 513 * 520;
#pragma unroll
    for (int r = 0; r < 4; ++r) {
        int dr = d0 + ty * 4 + r;
        if (dr >= 513) continue;
#pragma unroll
        for (int c = 0; c < 4; ++c) {
            int e = e0 + tx * 4 + c;
            if (e >= 513) continue;
            float val = v[r][c];
            if (dr == e) val += 25.0f;
            A[dr * 520 + e] = val;
            if (ti != tj) A[e * 520 + dr] = val;
        }
    }
}

// ---------------------------------------------------------------------------
// Phase 2b: HtU -> column 513 of A.  EXACT R3 numerics (sequential (r,c) sum
// per column) — do NOT reassociate; the solve amplifies RHS perturbations.
// ---------------------------------------------------------------------------
__global__ __launch_bounds__(256) void htu_kernel(const float* __restrict__ x)
{
    const int b = (int)blockIdx.x;
    const int dcol = (int)blockIdx.y * 256 + (int)threadIdx.x;
    if (dcol >= 513) return;
    const float* __restrict__ xb = x + b * 4096;
    float acc = 0.f;
    if (dcol < 256) {
        for (int r = 0; r < 63; ++r)
            for (int c = 0; c < 63; ++c)
                acc += xb[(r + 1) * 64 + c + 1] *
                       g_state[(((r + 1) * 64 + c) * 64 + b) * 256 + dcol];
    } else if (dcol < 512) {
        const int d2 = dcol - 256;
        for (int r = 0; r < 63; ++r)
            for (int c = 0; c < 63; ++c)
                acc += xb[(r + 1) * 64 + c + 1] *
                       g_state[((r * 64 + (c + 1)) * 64 + b) * 256 + d2];
    } else {
        for (int r = 0; r < 63; ++r)
            for (int c = 0; c < 63; ++c)
                acc += xb[(r + 1) * 64 + c + 1];
    }
    g_A[(b * 513 + dcol) * 520 + 513] = acc;
}

// ---------------------------------------------------------------------------
// Phase 3: per-batch blocked LU (no pivoting; SPD) + back substitution.
// ---------------------------------------------------------------------------
__global__ __launch_bounds__(512) void solve_kernel(float* __restrict__ out)
{
    __shared__ float P[513 * 17];
    __shared__ __align__(16) float Us[16 * 132];
    __shared__ float red[16];

    const int b = (int)blockIdx.x;
    const int tid = (int)threadIdx.x;
    float* __restrict__ A = g_A + b * 513 * 520;

    for (int k0 = 0; k0 < 513; k0 += 16) {
        const int nb = (513 - k0) < 16 ? (513 - k0) : 16;
        const int nrows = 513 - k0;

        for (int idx = tid; idx < nrows * nb; idx += 512) {
            int rr = idx / nb, cc = idx - rr * nb;
            P[rr * 17 + cc] = A[(k0 + rr) * 520 + (k0 + cc)];
        }
        __syncthreads();

        for (int kk = 0; kk < nb; ++kk) {
            float inv = 1.0f / P[kk * 17 + kk];
            for (int rr = kk + 1 + tid; rr < nrows; rr += 512) {
                float lv = P[rr * 17 + kk] * inv;
                P[rr * 17 + kk] = lv;
                for (int cc = kk + 1; cc < nb; ++cc)
                    P[rr * 17 + cc] -= lv * P[kk * 17 + cc];
            }
            __syncthreads();
        }

        for (int idx = tid; idx < nrows * nb; idx += 512) {
            int rr = idx / nb, cc = idx - rr * nb;
            A[(k0 + rr) * 520 + (k0 + cc)] = P[rr * 17 + cc];
        }
        __syncthreads();

        const int cstart = k0 + nb;
        const int width = 514 - cstart;
        for (int ch = 0; ch < width; ch += 128) {
            int wlen = width - ch; if (wlen > 128) wlen = 128;
            const int wlenp = (wlen + 3) & ~3;
            const int cbase = cstart + ch;

            for (int idx = tid; idx < nb * wlenp; idx += 512) {
                int rr = idx / wlenp, cc = idx - rr * wlenp;
                Us[rr * 132 + cc] = A[(k0 + rr) * 520 + cbase + cc];
            }
            __syncthreads();

            for (int cc = tid; cc < wlenp; cc += 512) {
                float col[16];
                for (int m = 0; m < nb; ++m) col[m] = Us[m * 132 + cc];
                for (int kk = 1; kk < nb; ++kk) {
                    float v = col[kk];
                    for (int m = 0; m < kk; ++m) v -= P[kk * 17 + m] * col[m];
                    col[kk] = v;
                }
                for (int m = 0; m < nb; ++m) {
                    Us[m * 132 + cc] = col[m];
                    A[(k0 + m) * 520 + cbase + cc] = col[m];
                }
            }
            __syncthreads();

            const int trows = nrows - nb;
            const int npr = (trows + 1) >> 1;
            const int ncq = wlenp >> 2;
            for (int idx = tid; idx < npr * ncq; idx += 512) {
                int pr = idx / ncq, cq = idx - pr * ncq;
                int row0 = cstart + pr * 2;
                int cc = cq * 4;
                bool has2 = (pr * 2 + 1) < trows;
                const unsigned long long* pa0 =
                    (const unsigned long long*)&A[row0 * 520 + cbase + cc];
                const unsigned long long* pa1 =
                    (const unsigned long long*)&A[(row0 + 1) * 520 + cbase + cc];
                unsigned long long a00 = pa0[0], a01v = pa0[1];
                unsigned long long a10 = has2 ? pa1[0] : a00;
                unsigned long long a11 = has2 ? pa1[1] : a01v;
                const float* P0 = &P[(row0 - k0) * 17];
                const float* P1 = has2 ? (P0 + 17) : P0;
#pragma unroll
                for (int m = 0; m < 16; ++m) {
                    if (m < nb) {
                        const unsigned long long* pu =
                            (const unsigned long long*)&Us[m * 132 + cc];
                        unsigned long long u01 = pu[0], u23 = pu[1];
                        float p0 = P0[m], p1 = P1[m];
                        unsigned long long np0 = pk2(-p0, -p0);
                        unsigned long long np1 = pk2(-p1, -p1);
                        fma2(a00, u01, np0); fma2(a01v, u23, np0);
                        fma2(a10, u01, np1); fma2(a11, u23, np1);
                    }
                }
                unsigned long long* sa0 =
                    (unsigned long long*)&A[row0 * 520 + cbase + cc];
                sa0[0] = a00; sa0[1] = a01v;
                if (has2) {
                    unsigned long long* sa1 =
                        (unsigned long long*)&A[(row0 + 1) * 520 + cbase + cc];
                    sa1[0] = a10; sa1[1] = a11;
                }
            }
            __syncthreads();
        }
    }

    float* xs = P;
    const int lane = tid & 31, wid = tid >> 5;
    for (int r = 512; r >= 0; --r) {
        float part = 0.f;
        for (int c = r + 1 + tid; c <= 512; c += 512)
            part += A[r * 520 + c] * xs[c];
#pragma unroll
        for (int off = 16; off > 0; off >>= 1)
            part += __shfl_down_sync(0xffffffffu, part, off);
        if (lane == 0) red[wid] = part;
        __syncthreads();
        if (tid == 0) {
            float s = 0.f;
#pragma unroll
            for (int w2 = 0; w2 < 16; ++w2) s += red[w2];
            xs[r] = (A[r * 520 + 513] - s) / A[r * 520 + r];
        }
        __syncthreads();
    }
    for (int i2 = tid; i2 < 513; i2 += 512)
        out[b * 513 + i2] = xs[i2];
}

// ---------------------------------------------------------------------------
extern "C" void kernel_launch(void* const* d_in, const int* in_sizes, int n_in,
                              void* d_out, int out_size)
{
    const float* x   = (const float*)d_in[0];
    const float* Win = (const float*)d_in[1];
    const float* W1  = (const float*)d_in[2];
    const float* W2  = (const float*)d_in[3];
    float* out = (float*)d_out;

    cudaFuncSetAttribute(scan_diag,
                         cudaFuncAttributeMaxDynamicSharedMemorySize, SCAN_SMEM);

    for (int d = 0; d < 127; ++d) {
        int i_min = d > 63 ? d - 63 : 0;
        int cells = (d <= 63) ? (d + 1) : (127 - d);
        scan_diag<<<dim3(cells, 2, 2), 256, SCAN_SMEM>>>(x, Win, W1, W2, d, i_min);
    }
    hth_kernel<<<dim3(45, 64), 256>>>();
    htu_kernel<<<dim3(64, 3), 256>>>(x);
    solve_kernel<<<64, 512>>>(out);
}

// round 9
// speedup vs baseline: 1.2559x; 1.0855x over previous
#include <cuda_runtime.h>

// Problem constants: B=64, H=64, W=64, n=256, NF=513, L=63*63=3969, alpha^2=25

__device__ float g_state[64 * 64 * 64 * 256];   // [cell=(i*64+j)][b][n]
__device__ float g_A[64 * 513 * 520];           // augmented [513 x 514] per batch, ld=520
__device__ unsigned int g_flags[64 * 64];       // per-cell completion counters (to 4)

// ---- packed f32x2 helpers (dual fp32 pipe) ---------------------------------
__device__ __forceinline__ unsigned long long pk2(float a, float b) {
    unsigned long long r;
    asm("mov.b64 %0,{%1,%2};" : "=l"(r) : "f"(a), "f"(b));
    return r;
}
__device__ __forceinline__ void fma2(unsigned long long& d,
                                     unsigned long long a, unsigned long long b) {
    asm("fma.rn.f32x2 %0,%1,%2,%0;" : "+l"(d) : "l"(a), "l"(b));
}
__device__ __forceinline__ void unpk2(unsigned long long v, float& a, float& b) {
    asm("mov.b64 {%0,%1},%2;" : "=f"(a), "=f"(b) : "l"(v));
}

// ---- gpu-scope release/acquire flag ops ------------------------------------
__device__ __forceinline__ unsigned int ld_acq(const unsigned int* p) {
    unsigned int v;
    asm volatile("ld.acquire.gpu.global.u32 %0,[%1];" : "=r"(v) : "l"(p) : "memory");
    return v;
}
__device__ __forceinline__ void red_rel(unsigned int* p) {
    asm volatile("red.release.gpu.global.add.u32 [%0],%1;" :: "l"(p), "r"(1u) : "memory");
}

__global__ void zero_flags()
{
    int idx = blockIdx.x * blockDim.x + threadIdx.x;
    if (idx < 64 * 64) g_flags[idx] = 0u;
}

// ---------------------------------------------------------------------------
// Phase 1: persistent wavefront scan with SMEM-RESIDENT W.  ONE launch.
// grid = 128 blocks = 32 row-groups x 4 n-slices (64 features each).
// Block (g, s) processes rows g and g+32, all 64 batches, features s*64..+63.
// W slice (512 x 64 = 128 KB) loaded ONCE into smem, resident across cells.
// Inputs (left/up states, 64k x 64b chunks) double-buffered (34 KB).
// All 128 blocks co-resident (1/SM) -> deadlock-free under any scheduler.
// Per-output accumulation: ONE accumulator, k ascending 0..511 -> states
// bitwise identical to the R2 passing build.
// ---------------------------------------------------------------------------
#define SCAN_SMEM (512 * 64 * 4 + 2 * 64 * 66 * 4)   // 131072 + 33792 = 164864

__global__ __launch_bounds__(256) void scan_persist(
    const float* __restrict__ x, const float* __restrict__ Win,
    const float* __restrict__ W1, const float* __restrict__ W2)
{
    extern __shared__ float sm[];
    float* w_s  = sm;                 // [512][64]
    float* in_s = sm + 512 * 64;      // [2][64][66]

    const int bid = (int)blockIdx.x;
    const int rg = bid >> 2;          // 0..31
    const int n0 = (bid & 3) * 64;

    const int tid = (int)threadIdx.x;
    const int nx = tid & 31;          // n-pair: n0 + nx*2, +1
    const int by = tid >> 5;          // batch group: by*8 .. +7

    // ---- load resident W slice: rows k=0..255 from W1, 256..511 from W2 ----
    for (int idx = tid; idx < 512 * 16; idx += 256) {
        int k = idx >> 4, q = idx & 15;
        const float* __restrict__ Wm = (k < 256) ? W1 : W2;
        int kk = (k < 256) ? k : k - 256;
        *(float4*)&w_s[k * 64 + q * 4] = *(const float4*)&Wm[kk * 256 + n0 + q * 4];
    }
    __syncthreads();

    const float2 win2 = *(const float2*)&Win[n0 + nx * 2];

    const int bb = tid & 63;          // staging batch
    const int kq = tid >> 6;          // staging k-16-group (0..3)

    for (int rr = 0; rr < 2; ++rr) {
        const int i = rg + rr * 32;
        const bool hasU = (i > 0);

        for (int j = 0; j < 64; ++j) {
            // wait: up cell (i-1,j) and left cell (i,j-1) fully published
            if (tid == 0) {
                if (hasU) {
                    const unsigned int* f = &g_flags[(i - 1) * 64 + j];
                    while (ld_acq(f) < 4u) __nanosleep(32);
                }
                if (j > 0) {
                    const unsigned int* f = &g_flags[i * 64 + (j - 1)];
                    while (ld_acq(f) < 4u) __nanosleep(32);
                }
            }
            __syncthreads();

            const bool hasL = (j > 0);
            const int cellL = hasL ? ((i * 64 + (j - 1)) * 64) : 0;
            const int cellU = hasU ? (((i - 1) * 64 + j) * 64) : 0;

            unsigned long long acc[4][2];
#pragma unroll
            for (int p = 0; p < 4; ++p) { acc[p][0] = 0ull; acc[p][1] = 0ull; }

            float4 v[4];
            auto LOADC = [&](int kc) {
                const bool isLeft = (kc < 4);
                const bool has = isLeft ? hasL : hasU;
                const int ks = isLeft ? kc * 64 : kc * 64 - 256;
                const int cell = isLeft ? cellL : cellU;
#pragma unroll
                for (int h = 0; h < 4; ++h) {
                    v[h] = make_float4(0.f, 0.f, 0.f, 0.f);
                    if (has)
                        v[h] = *(const float4*)
                            &g_state[(cell + bb) * 256 + ks + kq * 16 + h * 4];
                }
            };
            auto STOREC = [&](int buf) {
#pragma unroll
                for (int h = 0; h < 4; ++h) {
                    const int k = kq * 16 + h * 4;
                    float* ip = in_s + (buf * 64 + k) * 66 + bb;
                    ip[0 * 66] = v[h].x;
                    ip[1 * 66] = v[h].y;
                    ip[2 * 66] = v[h].z;
                    ip[3 * 66] = v[h].w;
                }
            };

            LOADC(0);
            STOREC(0);

            for (int kc = 0; kc < 8; ++kc) {
                __syncthreads();
                if (kc < 7) LOADC(kc + 1);
                const float* __restrict__ wr = w_s + kc * 64 * 64;
                const float* __restrict__ ir = in_s + ((kc & 1) * 64) * 66;
#pragma unroll 8
                for (int kl = 0; kl < 64; ++kl) {
                    unsigned long long a01 =
                        *(const unsigned long long*)&ir[kl * 66 + by * 8 + 0];
                    unsigned long long a23 =
                        *(const unsigned long long*)&ir[kl * 66 + by * 8 + 2];
                    unsigned long long a45 =
                        *(const unsigned long long*)&ir[kl * 66 + by * 8 + 4];
                    unsigned long long a67 =
                        *(const unsigned long long*)&ir[kl * 66 + by * 8 + 6];
                    float2 w2 = *(const float2*)&wr[kl * 64 + nx * 2];
                    unsigned long long w0 = pk2(w2.x, w2.x);
                    unsigned long long w1 = pk2(w2.y, w2.y);
                    fma2(acc[0][0], a01, w0); fma2(acc[0][1], a01, w1);
                    fma2(acc[1][0], a23, w0); fma2(acc[1][1], a23, w1);
                    fma2(acc[2][0], a45, w0); fma2(acc[2][1], a45, w1);
                    fma2(acc[3][0], a67, w0); fma2(acc[3][1], a67, w1);
                }
                if (kc < 7) STOREC((kc + 1) & 1);
            }

            // epilogue: + x*Win, tanh, store our 64-feature slice
            const int cell = (i * 64 + j) * 64;
#pragma unroll
            for (int p = 0; p < 4; ++p) {
                const int b = by * 8 + p * 2;
                const float xA = x[(b * 64 + i) * 64 + j];
                const float xB = x[((b + 1) * 64 + i) * 64 + j];
                float vA0, vB0, vA1, vB1;
                unpk2(acc[p][0], vA0, vB0);
                unpk2(acc[p][1], vA1, vB1);
                float2 oA, oB;
                oA.x = tanhf(vA0 + xA * win2.x);
                oA.y = tanhf(vA1 + xA * win2.y);
                oB.x = tanhf(vB0 + xB * win2.x);
                oB.y = tanhf(vB1 + xB * win2.y);
                *(float2*)&g_state[(cell + b) * 256 + n0 + nx * 2] = oA;
                *(float2*)&g_state[(cell + b + 1) * 256 + n0 + nx * 2] = oB;
            }

            __threadfence();
            __syncthreads();
            if (tid == 0) red_rel(&g_flags[i * 64 + j]);
        }
    }
}

// ---------------------------------------------------------------------------
// Phase 2a: HtH tiles -> both triangles of A, += 25 on diagonal.
// (verbatim from passing build)
// ---------------------------------------------------------------------------
__global__ __launch_bounds__(256) void hth_kernel()
{
    __shared__ __align__(16) float Hd[32][64];
    __shared__ __align__(16) float He[32][64];

    int rem = (int)blockIdx.x;
    int ti = 0;
    while (rem >= 9 - ti) { rem -= 9 - ti; ++ti; }
    const int tj = ti + rem;
    const int b = (int)blockIdx.y;
    const int d0 = ti * 64, e0 = tj * 64;
    const bool dLeft = d0 < 256, dOnes = d0 >= 512;
    const bool eLeft = e0 < 256, eOnes = e0 >= 512;
    const int dColn = dLeft ? d0 : d0 - 256;
    const int eColn = eLeft ? e0 : e0 - 256;

    const int tid = (int)threadIdx.x;
    const int tx = tid & 15, ty = tid >> 4;
    const int dd = tid & 63, kb = tid >> 6;

    int rs[8], cs[8];
#pragma unroll
    for (int t = 0; t < 8; ++t) { rs[t] = 0; cs[t] = kb + t * 4; }

    unsigned long long acc[2][4];
#pragma unroll
    for (int p = 0; p < 2; ++p)
#pragma unroll
        for (int c = 0; c < 4; ++c) acc[p][c] = 0ull;

    for (int l0 = 0; l0 < 3969; l0 += 32) {
        __syncthreads();
#pragma unroll
        for (int t = 0; t < 8; ++t) {
            const int kk = kb + t * 4;
            const int r = rs[t], c = cs[t];
            const bool valid = (r < 63);
            float vd, ve;
            if (dOnes) {
                vd = (valid && dd == 0) ? 1.f : 0.f;
            } else {
                int cellb = dLeft ? ((r + 1) * 64 + c) : (r * 64 + c + 1);
                vd = valid ? g_state[(cellb * 64 + b) * 256 + dColn + dd] : 0.f;
            }
            if (eOnes) {
                ve = (valid && dd == 0) ? 1.f : 0.f;
            } else {
                int cellb = eLeft ? ((r + 1) * 64 + c) : (r * 64 + c + 1);
                ve = valid ? g_state[(cellb * 64 + b) * 256 + eColn + dd] : 0.f;
            }
            Hd[kk][dd] = vd;
            He[kk][dd] = ve;
            int cn = c + 32, rn = r;
            if (cn >= 63) { cn -= 63; ++rn; }
            rs[t] = rn; cs[t] = cn;
        }
        __syncthreads();
#pragma unroll 8
        for (int kk = 0; kk < 32; ++kk) {
            unsigned long long a01 = *(const unsigned long long*)&Hd[kk][ty * 4];
            unsigned long long a23 = *(const unsigned long long*)&Hd[kk][ty * 4 + 2];
            float4 w = *(const float4*)&He[kk][tx * 4];
            unsigned long long wx = pk2(w.x, w.x);
            unsigned long long wy = pk2(w.y, w.y);
            unsigned long long wz = pk2(w.z, w.z);
            unsigned long long ww = pk2(w.w, w.w);
            fma2(acc[0][0], a01, wx); fma2(acc[0][1], a01, wy);
            fma2(acc[0][2], a01, wz); fma2(acc[0][3], a01, ww);
            fma2(acc[1][0], a23, wx); fma2(acc[1][1], a23, wy);
            fma2(acc[1][2], a23, wz); fma2(acc[1][3], a23, ww);
        }
    }

    float v[4][4];
#pragma unroll
    for (int p = 0; p < 2; ++p)
#pragma unroll
        for (int c = 0; c < 4; ++c)
            unpk2(acc[p][c], v[2 * p][c], v[2 * p + 1][c]);

    float* __restrict__ A = g_A + b * 513 * 520;
#pragma unroll
    for (int r = 0; r < 4; ++r) {
        int dr = d0 + ty * 4 + r;
        if (dr >= 513) continue;
#pragma unroll
        for (int c = 0; c < 4; ++c) {
            int e = e0 + tx * 4 + c;
            if (e >= 513) continue;
            float val = v[r][c];
            if (dr == e) val += 25.0f;
            A[dr * 520 + e] = val;
            if (ti != tj) A[e * 520 + dr] = val;
        }
    }
}

// ---------------------------------------------------------------------------
// Phase 2b: HtU -> column 513 of A.  EXACT sequential (r,c) numerics — do NOT
// reassociate; the solve amplifies RHS perturbations (R4 lesson).
// ---------------------------------------------------------------------------
__global__ __launch_bounds__(256) void htu_kernel(const float* __restrict__ x)
{
    const int b = (int)blockIdx.x;
    const int dcol = (int)blockIdx.y * 256 + (int)threadIdx.x;
    if (dcol >= 513) return;
    const float* __restrict__ xb = x + b * 4096;
    float acc = 0.f;
    if (dcol < 256) {
        for (int r = 0; r < 63; ++r)
            for (int c = 0; c < 63; ++c)
                acc += xb[(r + 1) * 64 + c + 1] *
                       g_state[(((r + 1) * 64 + c) * 64 + b) * 256 + dcol];
    } else if (dcol < 512) {
        const int d2 = dcol - 256;
        for (int r = 0; r < 63; ++r)
            for (int c = 0; c < 63; ++c)
                acc += xb[(r + 1) * 64 + c + 1] *
                       g_state[((r * 64 + (c + 1)) * 64 + b) * 256 + d2];
    } else {
        for (int r = 0; r < 63; ++r)
            for (int c = 0; c < 63; ++c)
                acc += xb[(r + 1) * 64 + c + 1];
    }
    g_A[(b * 513 + dcol) * 520 + 513] = acc;
}

// ---------------------------------------------------------------------------
// Phase 3: per-batch blocked LU (no pivoting; SPD) + back substitution.
// (verbatim from passing build)
// ---------------------------------------------------------------------------
__global__ __launch_bounds__(512) void solve_kernel(float* __restrict__ out)
{
    __shared__ float P[513 * 17];
    __shared__ __align__(16) float Us[16 * 132];
    __shared__ float red[16];

    const int b = (int)blockIdx.x;
    const int tid = (int)threadIdx.x;
    float* __restrict__ A = g_A + b * 513 * 520;

    for (int k0 = 0; k0 < 513; k0 += 16) {
        const int nb = (513 - k0) < 16 ? (513 - k0) : 16;
        const int nrows = 513 - k0;

        for (int idx = tid; idx < nrows * nb; idx += 512) {
            int rr = idx / nb, cc = idx - rr * nb;
            P[rr * 17 + cc] = A[(k0 + rr) * 520 + (k0 + cc)];
        }
        __syncthreads();

        for (int kk = 0; kk < nb; ++kk) {
            float inv = 1.0f / P[kk * 17 + kk];
            for (int rr = kk + 1 + tid; rr < nrows; rr += 512) {
                float lv = P[rr * 17 + kk] * inv;
                P[rr * 17 + kk] = lv;
                for (int cc = kk + 1; cc < nb; ++cc)
                    P[rr * 17 + cc] -= lv * P[kk * 17 + cc];
            }
            __syncthreads();
        }

        for (int idx = tid; idx < nrows * nb; idx += 512) {
            int rr = idx / nb, cc = idx - rr * nb;
            A[(k0 + rr) * 520 + (k0 + cc)] = P[rr * 17 + cc];
        }
        __syncthreads();

        const int cstart = k0 + nb;
        const int width = 514 - cstart;
        for (int ch = 0; ch < width; ch += 128) {
            int wlen = width - ch; if (wlen > 128) wlen = 128;
            const int wlenp = (wlen + 3) & ~3;
            const int cbase = cstart + ch;

            for (int idx = tid; idx < nb * wlenp; idx += 512) {
                int rr = idx / wlenp, cc = idx - rr * wlenp;
                Us[rr * 132 + cc] = A[(k0 + rr) * 520 + cbase + cc];
            }
            __syncthreads();

            for (int cc = tid; cc < wlenp; cc += 512) {
                float col[16];
                for (int m = 0; m < nb; ++m) col[m] = Us[m * 132 + cc];
                for (int kk = 1; kk < nb; ++kk) {
                    float v = col[kk];
                    for (int m = 0; m < kk; ++m) v -= P[kk * 17 + m] * col[m];
                    col[kk] = v;
                }
                for (int m = 0; m < nb; ++m) {
                    Us[m * 132 + cc] = col[m];
                    A[(k0 + m) * 520 + cbase + cc] = col[m];
                }
            }
            __syncthreads();

            const int trows = nrows - nb;
            const int npr = (trows + 1) >> 1;
            const int ncq = wlenp >> 2;
            for (int idx = tid; idx < npr * ncq; idx += 512) {
                int pr = idx / ncq, cq = idx - pr * ncq;
                int row0 = cstart + pr * 2;
                int cc = cq * 4;
                bool has2 = (pr * 2 + 1) < trows;
                const unsigned long long* pa0 =
                    (const unsigned long long*)&A[row0 * 520 + cbase + cc];
                const unsigned long long* pa1 =
                    (const unsigned long long*)&A[(row0 + 1) * 520 + cbase + cc];
                unsigned long long a00 = pa0[0], a01v = pa0[1];
                unsigned long long a10 = has2 ? pa1[0] : a00;
                unsigned long long a11 = has2 ? pa1[1] : a01v;
                const float* P0 = &P[(row0 - k0) * 17];
                const float* P1 = has2 ? (P0 + 17) : P0;
#pragma unroll
                for (int m = 0; m < 16; ++m) {
                    if (m < nb) {
                        const unsigned long long* pu =
                            (const unsigned long long*)&Us[m * 132 + cc];
                        unsigned long long u01 = pu[0], u23 = pu[1];
                        float p0 = P0[m], p1 = P1[m];
                        unsigned long long np0 = pk2(-p0, -p0);
                        unsigned long long np1 = pk2(-p1, -p1);
                        fma2(a00, u01, np0); fma2(a01v, u23, np0);
                        fma2(a10, u01, np1); fma2(a11, u23, np1);
                    }
                }
                unsigned long long* sa0 =
                    (unsigned long long*)&A[row0 * 520 + cbase + cc];
                sa0[0] = a00; sa0[1] = a01v;
                if (has2) {
                    unsigned long long* sa1 =
                        (unsigned long long*)&A[(row0 + 1) * 520 + cbase + cc];
                    sa1[0] = a10; sa1[1] = a11;
                }
            }
            __syncthreads();
        }
    }

    float* xs = P;
    const int lane = tid & 31, wid = tid >> 5;
    for (int r = 512; r >= 0; --r) {
        float part = 0.f;
        for (int c = r + 1 + tid; c <= 512; c += 512)
            part += A[r * 520 + c] * xs[c];
#pragma unroll
        for (int off = 16; off > 0; off >>= 1)
            part += __shfl_down_sync(0xffffffffu, part, off);
        if (lane == 0) red[wid] = part;
        __syncthreads();
        if (tid == 0) {
            float s = 0.f;
#pragma unroll
            for (int w2 = 0; w2 < 16; ++w2) s += red[w2];
            xs[r] = (A[r * 520 + 513] - s) / A[r * 520 + r];
        }
        __syncthreads();
    }
    for (int i2 = tid; i2 < 513; i2 += 512)
        out[b * 513 + i2] = xs[i2];
}

// ---------------------------------------------------------------------------
extern "C" void kernel_launch(void* const* d_in, const int* in_sizes, int n_in,
                              void* d_out, int out_size)
{
    const float* x   = (const float*)d_in[0];
    const float* Win = (const float*)d_in[1];
    const float* W1  = (const float*)d_in[2];
    const float* W2  = (const float*)d_in[3];
    float* out = (float*)d_out;

    cudaFuncSetAttribute(scan_persist,
                         cudaFuncAttributeMaxDynamicSharedMemorySize, SCAN_SMEM);

    zero_flags<<<8, 512>>>();
    scan_persist<<<128, 256, SCAN_SMEM>>>(x, Win, W1, W2);
    hth_kernel<<<dim3(45, 64), 256>>>();
    htu_kernel<<<dim3(64, 3), 256>>>(x);
    solve_kernel<<<64, 512>>>(out);
}